// round 16
// baseline (speedup 1.0000x reference)
#include <cuda_runtime.h>
#include <cuda_bf16.h>
#include <cstdint>

typedef unsigned long long ull;

#define N_PTS 8192
#define DIM   128
#define EMB   16

// Scratch (device globals — no allocation allowed)
__device__ __align__(16) float g_z[N_PTS * EMB];
__device__ float g_sq[N_PTS];
__device__ float g_rowsum[N_PTS];

__device__ __forceinline__ float frcp(float x) {
    float r; asm("rcp.approx.ftz.f32 %0, %1;" : "=f"(r) : "f"(x)); return r;
}
__device__ __forceinline__ void fma2(ull &d, ull a, ull b) {
    asm("fma.rn.f32x2 %0, %1, %2, %0;" : "+l"(d) : "l"(a), "l"(b));
}
__device__ __forceinline__ ull add2(ull a, ull b) {
    ull d; asm("add.rn.f32x2 %0, %1, %2;" : "=l"(d) : "l"(a), "l"(b)); return d;
}
__device__ __forceinline__ ull mul2(ull a, ull b) {
    ull d; asm("mul.rn.f32x2 %0, %1, %2;" : "=l"(d) : "l"(a), "l"(b)); return d;
}
__device__ __forceinline__ void unpack2(ull v, float &lo, float &hi) {
    asm("mov.b64 {%0, %1}, %2;" : "=f"(lo), "=f"(hi) : "l"(v));
}
__device__ __forceinline__ ull bcast2(float x) {
    ull v; asm("mov.b64 %0, {%1, %1};" : "=l"(v) : "f"(x)); return v;
}
__device__ __forceinline__ ull pack2f(float lo, float hi) {
    ull v; asm("mov.b64 %0, {%1, %2};" : "=l"(v) : "f"(lo), "f"(hi)); return v;
}

// triangular decode, 64x64 grid of 128x128 tiles (2080 blocks)
__device__ __forceinline__ int tri_off(int r) { return (r * (129 - r)) >> 1; }
__device__ __forceinline__ void tri_decode(int b, int &r, int &c) {
    int rr = (int)((129.0f - sqrtf(16641.0f - 8.0f * (float)b)) * 0.5f);
    if (rr < 0) rr = 0;
    if (rr > 63) rr = 63;
    while (rr < 63 && tri_off(rr + 1) <= b) rr++;
    while (rr > 0 && tri_off(rr) > b) rr--;
    r = rr; c = rr + (b - tri_off(rr));
}

// ===========================================================================
// Kernel 0: zero rowsum accumulators
// ===========================================================================
__global__ void zero_kernel()
{
    int gid = blockIdx.x * 1024 + threadIdx.x;
    if (gid < N_PTS) g_rowsum[gid] = 0.0f;
}

// ===========================================================================
// Encoder: 256 blocks x 256 threads, 32 rows/block (measured 15.5us)
// ===========================================================================
#define OFF_W1   0
#define OFF_X    32768
#define OFF_W2   49664
#define OFF_W3   57856
#define OFF_W4   59904
#define OFF_B1   60928
#define OFF_B2   61184
#define OFF_B3   61312
#define OFF_B4   61376
#define OFF_E1   61440
#define OFF_E2   70144
#define OFF_E3   74752
#define ENC_SMEM 77312

__global__ __launch_bounds__(256) void encoder_kernel(
    const float* __restrict__ x,
    const float* __restrict__ W1, const float* __restrict__ b1,
    const float* __restrict__ W2, const float* __restrict__ b2,
    const float* __restrict__ W3, const float* __restrict__ b3,
    const float* __restrict__ W4, const float* __restrict__ b4)
{
    extern __shared__ char dyn[];
    float* sW1 = (float*)(dyn + OFF_W1);
    float* sx  = (float*)(dyn + OFF_X);
    float* sW2 = (float*)(dyn + OFF_W2);
    float* sW3 = (float*)(dyn + OFF_W3);
    float* sW4 = (float*)(dyn + OFF_W4);
    float* sb1 = (float*)(dyn + OFF_B1);
    float* sb2 = (float*)(dyn + OFF_B2);
    float* sb3 = (float*)(dyn + OFF_B3);
    float* sb4 = (float*)(dyn + OFF_B4);
    float* e1  = (float*)(dyn + OFF_E1);
    float* e2  = (float*)(dyn + OFF_E2);
    float* e3  = (float*)(dyn + OFF_E3);

    const int t  = threadIdx.x;
    const int i0 = blockIdx.x * 32;

    {
        const ulonglong2* s = (const ulonglong2*)W1;
        ulonglong2* d = (ulonglong2*)sW1;
        #pragma unroll
        for (int r = 0; r < 8; r++) d[t + r * 256] = s[t + r * 256];
    }
    {
        const float4* x4 = (const float4*)(x + (size_t)i0 * DIM);
        #pragma unroll
        for (int r = 0; r < 4; r++) {
            int idx = t + r * 256;
            *(float4*)&sx[(idx >> 5) * 132 + (idx & 31) * 4] = x4[idx];
        }
    }
    {
        const float4* s = (const float4*)W2;
        float4* d = (float4*)sW2;
        d[t] = s[t]; d[t + 256] = s[t + 256];
    }
    if (t < 128) ((float4*)sW3)[t] = ((const float4*)W3)[t];
    if (t < 64)  ((float4*)sW4)[t] = ((const float4*)W4)[t];
    if (t < 64) sb1[t] = b1[t];
    if (t < 32) sb2[t] = b2[t];
    if (t < 16) { sb3[t] = b3[t]; sb4[t] = b4[t]; }
    __syncthreads();

    {
        const int og = t & 15, rg = t >> 4;
        const int r0 = rg * 2, r1 = r0 + 1;
        ull a00 = ((const ull*)sb1)[og * 2];
        ull a01 = ((const ull*)sb1)[og * 2 + 1];
        ull a10 = a00, a11 = a01;
        const ull* w1u = (const ull*)sW1;
        #pragma unroll 4
        for (int k4 = 0; k4 < 32; k4++) {
            float4 x0 = *(const float4*)&sx[r0 * 132 + k4 * 4];
            float4 x1 = *(const float4*)&sx[r1 * 132 + k4 * 4];
            float xs0[4] = {x0.x, x0.y, x0.z, x0.w};
            float xs1[4] = {x1.x, x1.y, x1.z, x1.w};
            #pragma unroll
            for (int c = 0; c < 4; c++) {
                ulonglong2 w = *(const ulonglong2*)&w1u[(k4 * 4 + c) * 32 + og * 2];
                ull v0 = bcast2(xs0[c]);
                ull v1 = bcast2(xs1[c]);
                fma2(a00, v0, w.x); fma2(a01, v0, w.y);
                fma2(a10, v1, w.x); fma2(a11, v1, w.y);
            }
        }
        float p, q, r, s;
        unpack2(a00, p, q); unpack2(a01, r, s);
        *(float4*)&e1[r0 * 68 + og * 4] =
            make_float4(fmaxf(p, 0.f), fmaxf(q, 0.f), fmaxf(r, 0.f), fmaxf(s, 0.f));
        unpack2(a10, p, q); unpack2(a11, r, s);
        *(float4*)&e1[r1 * 68 + og * 4] =
            make_float4(fmaxf(p, 0.f), fmaxf(q, 0.f), fmaxf(r, 0.f), fmaxf(s, 0.f));
    }
    __syncthreads();

    const int row = t >> 3;
    const int e   = t & 7;

    {
        ull c0 = ((const ull*)sb2)[e * 2];
        ull c1 = ((const ull*)sb2)[e * 2 + 1];
        const float* h1r = &e1[row * 68];
        const ull* w2u = (const ull*)sW2;
        #pragma unroll 4
        for (int k4 = 0; k4 < 16; k4++) {
            float4 h = *(const float4*)&h1r[k4 * 4];
            float hs[4] = {h.x, h.y, h.z, h.w};
            #pragma unroll
            for (int c = 0; c < 4; c++) {
                ulonglong2 w = *(const ulonglong2*)&w2u[(k4 * 4 + c) * 16 + e * 2];
                ull hb = bcast2(hs[c]);
                fma2(c0, hb, w.x); fma2(c1, hb, w.y);
            }
        }
        float p, q, r, s;
        unpack2(c0, p, q); unpack2(c1, r, s);
        *(float4*)&e2[row * 36 + e * 4] =
            make_float4(fmaxf(p, 0.f), fmaxf(q, 0.f), fmaxf(r, 0.f), fmaxf(s, 0.f));
    }
    __syncthreads();

    {
        ull d0 = ((const ull*)sb3)[e];
        const float* h2r = &e2[row * 36];
        const ull* w3u = (const ull*)sW3;
        #pragma unroll
        for (int k4 = 0; k4 < 8; k4++) {
            float4 h = *(const float4*)&h2r[k4 * 4];
            float hs[4] = {h.x, h.y, h.z, h.w};
            #pragma unroll
            for (int c = 0; c < 4; c++)
                fma2(d0, bcast2(hs[c]), w3u[(k4 * 4 + c) * 8 + e]);
        }
        float p, q;
        unpack2(d0, p, q);
        *(float2*)&e3[row * 20 + e * 2] = make_float2(fmaxf(p, 0.f), fmaxf(q, 0.f));
    }
    __syncthreads();

    {
        ull f0 = ((const ull*)sb4)[e];
        const float* h3r = &e3[row * 20];
        const ull* w4u = (const ull*)sW4;
        #pragma unroll
        for (int k4 = 0; k4 < 4; k4++) {
            float4 h = *(const float4*)&h3r[k4 * 4];
            float hs[4] = {h.x, h.y, h.z, h.w};
            #pragma unroll
            for (int c = 0; c < 4; c++)
                fma2(f0, bcast2(hs[c]), w4u[(k4 * 4 + c) * 8 + e]);
        }
        float z0, z1;
        unpack2(f0, z0, z1);
        *(float2*)&g_z[(size_t)(i0 + row) * EMB + e * 2] = make_float2(z0, z1);

        float ps = z0 * z0 + z1 * z1;
        ps += __shfl_xor_sync(0xffffffffu, ps, 1);
        ps += __shfl_xor_sync(0xffffffffu, ps, 2);
        ps += __shfl_xor_sync(0xffffffffu, ps, 4);
        if (e == 0) g_sq[i0 + row] = ps;
    }
}

// ===========================================================================
// Shared 128x128-tile staging + mma88 (thread tile 8i x 8j; j = 8tx..8tx+7)
// ===========================================================================
__device__ __forceinline__ void stage_a128(ull (*zasm)[130], int r0, int t) {
    const float4* gz4 = (const float4*)g_z;
    #pragma unroll
    for (int rr = 0; rr < 2; rr++) {
        int idx = t + rr * 256;
        int row = idx >> 2, kq = idx & 3;
        float4 f = gz4[(size_t)(r0 + row) * 4 + kq];
        *(float2*)&zasm[2 * kq][row]     = make_float2(f.x, f.y);
        *(float2*)&zasm[2 * kq + 1][row] = make_float2(f.z, f.w);
    }
}

__device__ __forceinline__ void stage_b128(ull (*zbsm)[68], int j0, int t) {
    const float4* gz4 = (const float4*)g_z;
    #pragma unroll
    for (int rr = 0; rr < 2; rr++) {
        int idx = t + rr * 256;
        int row = idx >> 2, kq = idx & 3;
        float4 f = gz4[(size_t)(j0 + row) * 4 + kq];
        int jp = row >> 1, lane = row & 1;
        int c = jp >> 1;
        int slot = 2 * ((c >> 1) + 16 * (c & 1)) + (jp & 1);
        ((float*)&zbsm[4 * kq + 0][slot])[lane] = f.x;
        ((float*)&zbsm[4 * kq + 1][slot])[lane] = f.y;
        ((float*)&zbsm[4 * kq + 2][slot])[lane] = f.z;
        ((float*)&zbsm[4 * kq + 3][slot])[lane] = f.w;
    }
}

__device__ __forceinline__ void mma88(ull* acc, const ull (*zasm)[130],
                                      const ull (*zbsm)[68], int tx, int ty) {
    #pragma unroll
    for (int k2 = 0; k2 < 8; k2++) {
        ulonglong2 aA = *(const ulonglong2*)&zasm[k2][8 * ty];
        ulonglong2 aB = *(const ulonglong2*)&zasm[k2][8 * ty + 2];
        ulonglong2 aC = *(const ulonglong2*)&zasm[k2][8 * ty + 4];
        ulonglong2 aD = *(const ulonglong2*)&zasm[k2][8 * ty + 6];
        ull apk[8] = {aA.x, aA.y, aB.x, aB.y, aC.x, aC.y, aD.x, aD.y};
        ulonglong2 be0 = *(const ulonglong2*)&zbsm[2 * k2][2 * tx];
        ulonglong2 be1 = *(const ulonglong2*)&zbsm[2 * k2][32 + 2 * tx];
        ulonglong2 bo0 = *(const ulonglong2*)&zbsm[2 * k2 + 1][2 * tx];
        ulonglong2 bo1 = *(const ulonglong2*)&zbsm[2 * k2 + 1][32 + 2 * tx];
        ull be[4] = {be0.x, be0.y, be1.x, be1.y};
        ull bo[4] = {bo0.x, bo0.y, bo1.x, bo1.y};
        #pragma unroll
        for (int r = 0; r < 8; r++) {
            float alo, ahi;
            unpack2(apk[r], alo, ahi);
            ull ae = bcast2(alo);
            ull ao = bcast2(ahi);
            #pragma unroll
            for (int m = 0; m < 4; m++) {
                fma2(acc[r * 4 + m], ae, be[m]);
                fma2(acc[r * 4 + m], ao, bo[m]);
            }
        }
    }
}

// ===========================================================================
// Kernel 2: symmetric row sums. 2080 blocks, 256 threads (measured ~38us)
// ===========================================================================
__global__ __launch_bounds__(256, 2) void rowsum_kernel()
{
    int by, bx;
    tri_decode(blockIdx.x, by, bx);

    __shared__ __align__(16) ull zasm[8][130];
    __shared__ __align__(16) ull zbsm[16][68];
    __shared__ __align__(16) ull sq1jp[64];
    __shared__ float sqis[128];
    __shared__ float rowacc[128];
    __shared__ float colacc[128];

    const int t = threadIdx.x, tx = t & 15, ty = t >> 4;
    const int i0 = by * 128, j0 = bx * 128;
    const bool diag = (bx == by);

    stage_a128(zasm, i0, t);
    stage_b128(zbsm, j0, t);
    if (t < 128) { sqis[t] = g_sq[i0 + t]; colacc[t] = 0.0f; }
    else if (t < 192) {
        int jp = t - 128;
        sq1jp[jp] = pack2f(1.0f + g_sq[j0 + 2 * jp], 1.0f + g_sq[j0 + 2 * jp + 1]);
    }
    __syncthreads();

    ull acc[32];
    #pragma unroll
    for (int m = 0; m < 32; m++) acc[m] = 0ull;
    mma88(acc, zasm, zbsm, tx, ty);

    ulonglong2 sjA = *(const ulonglong2*)&sq1jp[4 * tx];
    ulonglong2 sjB = *(const ulonglong2*)&sq1jp[4 * tx + 2];
    ull sj[4] = {sjA.x, sjA.y, sjB.x, sjB.y};
    const ull neg2 = bcast2(-2.0f);
    ull colp[4] = {0ull, 0ull, 0ull, 0ull};

    #pragma unroll
    for (int r = 0; r < 8; r++) {
        ull sid = bcast2(sqis[8 * ty + r]);
        float prow = 0.0f;
        #pragma unroll
        for (int m = 0; m < 4; m++) {
            ull d = add2(sid, sj[m]);
            fma2(d, acc[r * 4 + m], neg2);
            float e0, e1;
            unpack2(d, e0, e1);
            float n0 = frcp(e0), n1 = frcp(e1);
            prow += n0 + n1;
            colp[m] = add2(colp[m], pack2f(n0, n1));
        }
        float v = prow;
        v += __shfl_xor_sync(0xffffffffu, v, 1);
        v += __shfl_xor_sync(0xffffffffu, v, 2);
        v += __shfl_xor_sync(0xffffffffu, v, 4);
        v += __shfl_xor_sync(0xffffffffu, v, 8);
        if (tx == 0) rowacc[8 * ty + r] = v;
    }

    if (!diag) {
        #pragma unroll
        for (int m = 0; m < 4; m++) {
            ull c = colp[m];
            ull cs = __shfl_xor_sync(0xffffffffu, c, 16);
            c = add2(c, cs);
            if ((t & 16) == 0) {
                float lo, hi;
                unpack2(c, lo, hi);
                atomicAdd(&colacc[8 * tx + 2 * m], lo);
                atomicAdd(&colacc[8 * tx + 2 * m + 1], hi);
            }
        }
    }
    __syncthreads();

    if (t < 128) atomicAdd(&g_rowsum[i0 + t], rowacc[t]);
    if (!diag && t >= 128) atomicAdd(&g_rowsum[j0 + (t - 128)], colacc[t - 128]);
}

// ===========================================================================
// Kernel 3: writer, 128x128 tiles (2080 blocks), 256 threads, mma88-based.
// snum[128][132] with XOR swizzle:
//   col(j,i) = 64*(j>>6) + ((j&63) ^ 4*((j>>5)&1) ^ 4*(i>>4) ^ 16*((i>>3)&1))
// -> bijective in j, float4-aligned, STS and transposed-gather conflict-free.
// Transposed stores: warp inst = 4 rows x dense 128B runs.
// ===========================================================================
#define WZA   0        // ull[8][130]      8320
#define WZB   8320     // ull[16][68]      8704
#define WSQJ  17024    // ull[64]           512
#define WSQI  17536    // float[128]        512
#define WRVI  18048    // float[128]        512
#define WRVJ  18560    // float[128]        512
#define WSN   19072    // float[128*132]  67584
#define WR_SMEM 86656

__global__ __launch_bounds__(256, 2) void writer_kernel(float* __restrict__ out)
{
    extern __shared__ char wsm[];
    ull (*zasm)[130] = (ull (*)[130])(wsm + WZA);
    ull (*zbsm)[68]  = (ull (*)[68])(wsm + WZB);
    ull*   sq1jp = (ull*)(wsm + WSQJ);
    float* sqis  = (float*)(wsm + WSQI);
    float* rinvi = (float*)(wsm + WRVI);
    float* rinvj = (float*)(wsm + WRVJ);
    float* snum  = (float*)(wsm + WSN);

    int by, bx;
    tri_decode(blockIdx.x, by, bx);

    const int t = threadIdx.x, tx = t & 15, ty = t >> 4;
    const int i0 = by * 128, j0 = bx * 128;
    const bool diag = (bx == by);

    stage_a128(zasm, i0, t);
    stage_b128(zbsm, j0, t);
    if (t < 128) {
        sqis[t]  = g_sq[i0 + t];
        rinvi[t] = frcp(g_rowsum[i0 + t]);
    } else {
        rinvj[t - 128] = frcp(g_rowsum[j0 + (t - 128)]);
    }
    if (t < 64)
        sq1jp[t] = pack2f(1.0f + g_sq[j0 + 2 * t], 1.0f + g_sq[j0 + 2 * t + 1]);
    __syncthreads();

    ull acc[32];
    #pragma unroll
    for (int m = 0; m < 32; m++) acc[m] = 0ull;
    mma88(acc, zasm, zbsm, tx, ty);

    ulonglong2 sjA = *(const ulonglong2*)&sq1jp[4 * tx];
    ulonglong2 sjB = *(const ulonglong2*)&sq1jp[4 * tx + 2];
    ull sj[4] = {sjA.x, sjA.y, sjB.x, sjB.y};
    const ull neg2 = bcast2(-2.0f);

    // j-base for this thread: 8*tx ; jl = base within 64-group, grp = tx>>3
    const int jbase = 8 * (tx & 7);
    const int jgrp  = tx >> 3;           // 0 or 1
    const int jb5   = (jbase >> 5) & 1;  // bit5 of j-low
    const int snoff = 64 * jgrp;

    #pragma unroll
    for (int r = 0; r < 8; r++) {
        const int irow = 8 * ty + r;
        ull sid = bcast2(sqis[irow]);
        ull rv  = bcast2(rinvi[irow]);
        ull n01, n23, n45, n67;
        {
            ull d0 = add2(sid, sj[0]); fma2(d0, acc[r * 4 + 0], neg2);
            ull d1 = add2(sid, sj[1]); fma2(d1, acc[r * 4 + 1], neg2);
            ull d2 = add2(sid, sj[2]); fma2(d2, acc[r * 4 + 2], neg2);
            ull d3 = add2(sid, sj[3]); fma2(d3, acc[r * 4 + 3], neg2);
            float e0, e1;
            unpack2(d0, e0, e1); n01 = pack2f(frcp(e0), frcp(e1));
            unpack2(d1, e0, e1); n23 = pack2f(frcp(e0), frcp(e1));
            unpack2(d2, e0, e1); n45 = pack2f(frcp(e0), frcp(e1));
            unpack2(d3, e0, e1); n67 = pack2f(frcp(e0), frcp(e1));
        }

        // snum staging (XOR swizzle)
        const int roti = (4 * (irow >> 4)) ^ (16 * ((irow >> 3) & 1));
        const int col0 = (jbase ^ (4 * jb5)) ^ roti;
        const int col4 = ((jbase + 4) ^ (4 * jb5)) ^ roti;
        {
            ulonglong2 s1; s1.x = n01; s1.y = n23;
            *(ulonglong2*)&snum[irow * 132 + snoff + col0] = s1;
            ulonglong2 s2; s2.x = n45; s2.y = n67;
            *(ulonglong2*)&snum[irow * 132 + snoff + col4] = s2;
        }

        // normal tile stores (2x STG.128, j = 8tx..8tx+7)
        {
            float* orow = &out[(size_t)(i0 + irow) * N_PTS + j0 + 8 * tx];
            ulonglong2 v1; v1.x = mul2(n01, rv); v1.y = mul2(n23, rv);
            ulonglong2 v2; v2.x = mul2(n45, rv); v2.y = mul2(n67, rv);
            *(ulonglong2*)&orow[0] = v1;
            *(ulonglong2*)&orow[4] = v2;
        }
    }

    if (!diag) {
        __syncthreads();
        // transposed tile: thread = (jr = t>>3 (+32*it), u = t&7 -> i chunk 16u)
        const int u = t & 7;
        const int jrb = t >> 3;   // 0..31
        #pragma unroll
        for (int it = 0; it < 4; it++) {
            const int jrow = jrb + 32 * it;
            const int jl = jrow & 63;
            const int g = jrow >> 6;
            const int jswz = jl ^ (4 * ((jl >> 5) & 1)) ^ (4 * u);
            const float rvj = rinvj[jrow];
            float* orow = &out[(size_t)(j0 + jrow) * N_PTS + i0 + 16 * u];
            #pragma unroll
            for (int q = 0; q < 4; q++) {
                const int colq = 64 * g + (jswz ^ (16 * (q >> 1)));
                const int ib = 16 * u + 4 * q;
                float4 v;
                v.x = snum[(ib + 0) * 132 + colq];
                v.y = snum[(ib + 1) * 132 + colq];
                v.z = snum[(ib + 2) * 132 + colq];
                v.w = snum[(ib + 3) * 132 + colq];
                v.x *= rvj; v.y *= rvj; v.z *= rvj; v.w *= rvj;
                *(float4*)&orow[4 * q] = v;
            }
        }
    }
}

// ---------------------------------------------------------------------------
extern "C" void kernel_launch(void* const* d_in, const int* in_sizes, int n_in,
                              void* d_out, int out_size)
{
    const float* x  = (const float*)d_in[0];
    const float* W1 = (const float*)d_in[1];
    const float* b1 = (const float*)d_in[2];
    const float* W2 = (const float*)d_in[3];
    const float* b2 = (const float*)d_in[4];
    const float* W3 = (const float*)d_in[5];
    const float* b3 = (const float*)d_in[6];
    const float* W4 = (const float*)d_in[7];
    const float* b4 = (const float*)d_in[8];
    float* out = (float*)d_out;

    cudaFuncSetAttribute(encoder_kernel,
                         cudaFuncAttributeMaxDynamicSharedMemorySize, ENC_SMEM);
    cudaFuncSetAttribute(writer_kernel,
                         cudaFuncAttributeMaxDynamicSharedMemorySize, WR_SMEM);

    const int n_tri = (64 * 65) / 2;  // 2080

    zero_kernel<<<8, 1024>>>();
    encoder_kernel<<<N_PTS / 32, 256, ENC_SMEM>>>(x, W1, b1, W2, b2, W3, b3, W4, b4);
    rowsum_kernel<<<n_tri, 256>>>();
    writer_kernel<<<n_tri, 256, WR_SMEM>>>(out);
}

// round 17
// speedup vs baseline: 1.1894x; 1.1894x over previous
#include <cuda_runtime.h>
#include <cuda_bf16.h>
#include <cstdint>

typedef unsigned long long ull;

#define N_PTS 8192
#define DIM   128
#define EMB   16

// Scratch (device globals — no allocation allowed)
__device__ __align__(16) float g_z[N_PTS * EMB];
__device__ float g_sq[N_PTS];
__device__ float g_rowsum[N_PTS];

__device__ __forceinline__ float frcp(float x) {
    float r; asm("rcp.approx.ftz.f32 %0, %1;" : "=f"(r) : "f"(x)); return r;
}
__device__ __forceinline__ void fma2(ull &d, ull a, ull b) {
    asm("fma.rn.f32x2 %0, %1, %2, %0;" : "+l"(d) : "l"(a), "l"(b));
}
__device__ __forceinline__ ull add2(ull a, ull b) {
    ull d; asm("add.rn.f32x2 %0, %1, %2;" : "=l"(d) : "l"(a), "l"(b)); return d;
}
__device__ __forceinline__ ull mul2(ull a, ull b) {
    ull d; asm("mul.rn.f32x2 %0, %1, %2;" : "=l"(d) : "l"(a), "l"(b)); return d;
}
__device__ __forceinline__ void unpack2(ull v, float &lo, float &hi) {
    asm("mov.b64 {%0, %1}, %2;" : "=f"(lo), "=f"(hi) : "l"(v));
}
__device__ __forceinline__ ull bcast2(float x) {
    ull v; asm("mov.b64 %0, {%1, %1};" : "=l"(v) : "f"(x)); return v;
}
__device__ __forceinline__ ull pack2f(float lo, float hi) {
    ull v; asm("mov.b64 %0, {%1, %2};" : "=l"(v) : "f"(lo), "f"(hi)); return v;
}

// 16B-chunk swizzle for the writer's b-tile (j = 4tx+c mapping)
__device__ __forceinline__ int bswz(int j) {
    return 2 * ((j >> 2) + ((j >> 1) & 1) * 16) + (j & 1);
}

// triangular decode, 64x64 grid of 128x128 tiles (2080 blocks) — rowsum
__device__ __forceinline__ int tri_off(int r) { return (r * (129 - r)) >> 1; }
__device__ __forceinline__ void tri_decode(int b, int &r, int &c) {
    int rr = (int)((129.0f - sqrtf(16641.0f - 8.0f * (float)b)) * 0.5f);
    if (rr < 0) rr = 0;
    if (rr > 63) rr = 63;
    while (rr < 63 && tri_off(rr + 1) <= b) rr++;
    while (rr > 0 && tri_off(rr) > b) rr--;
    r = rr; c = rr + (b - tri_off(rr));
}

// triangular decode, 128x128 grid of 64x64 tiles (8256 blocks) — writer
__device__ __forceinline__ int tri_off128(int r) { return (r * (257 - r)) >> 1; }
__device__ __forceinline__ void tri_decode128(int b, int &r, int &c) {
    int rr = (int)((257.0f - sqrtf(66049.0f - 8.0f * (float)b)) * 0.5f);
    if (rr < 0) rr = 0;
    if (rr > 127) rr = 127;
    while (rr < 127 && tri_off128(rr + 1) <= b) rr++;
    while (rr > 0 && tri_off128(rr) > b) rr--;
    r = rr; c = rr + (b - tri_off128(rr));
}

// ===========================================================================
// Encoder: 256 blocks x 256 threads, 32 rows/block (measured 15.5us).
// Also zeroes g_rowsum (merged zero kernel).
// ===========================================================================
#define OFF_W1   0
#define OFF_X    32768
#define OFF_W2   49664
#define OFF_W3   57856
#define OFF_W4   59904
#define OFF_B1   60928
#define OFF_B2   61184
#define OFF_B3   61312
#define OFF_B4   61376
#define OFF_E1   61440
#define OFF_E2   70144
#define OFF_E3   74752
#define ENC_SMEM 77312

__global__ __launch_bounds__(256) void encoder_kernel(
    const float* __restrict__ x,
    const float* __restrict__ W1, const float* __restrict__ b1,
    const float* __restrict__ W2, const float* __restrict__ b2,
    const float* __restrict__ W3, const float* __restrict__ b3,
    const float* __restrict__ W4, const float* __restrict__ b4)
{
    extern __shared__ char dyn[];
    float* sW1 = (float*)(dyn + OFF_W1);
    float* sx  = (float*)(dyn + OFF_X);
    float* sW2 = (float*)(dyn + OFF_W2);
    float* sW3 = (float*)(dyn + OFF_W3);
    float* sW4 = (float*)(dyn + OFF_W4);
    float* sb1 = (float*)(dyn + OFF_B1);
    float* sb2 = (float*)(dyn + OFF_B2);
    float* sb3 = (float*)(dyn + OFF_B3);
    float* sb4 = (float*)(dyn + OFF_B4);
    float* e1  = (float*)(dyn + OFF_E1);
    float* e2  = (float*)(dyn + OFF_E2);
    float* e3  = (float*)(dyn + OFF_E3);

    const int t  = threadIdx.x;
    const int i0 = blockIdx.x * 32;

    // zero rowsum accumulators (merged; consumed by rowsum kernel atomics)
    int gid = blockIdx.x * 256 + t;
    if (gid < N_PTS) g_rowsum[gid] = 0.0f;

    {
        const ulonglong2* s = (const ulonglong2*)W1;
        ulonglong2* d = (ulonglong2*)sW1;
        #pragma unroll
        for (int r = 0; r < 8; r++) d[t + r * 256] = s[t + r * 256];
    }
    {
        const float4* x4 = (const float4*)(x + (size_t)i0 * DIM);
        #pragma unroll
        for (int r = 0; r < 4; r++) {
            int idx = t + r * 256;
            *(float4*)&sx[(idx >> 5) * 132 + (idx & 31) * 4] = x4[idx];
        }
    }
    {
        const float4* s = (const float4*)W2;
        float4* d = (float4*)sW2;
        d[t] = s[t]; d[t + 256] = s[t + 256];
    }
    if (t < 128) ((float4*)sW3)[t] = ((const float4*)W3)[t];
    if (t < 64)  ((float4*)sW4)[t] = ((const float4*)W4)[t];
    if (t < 64) sb1[t] = b1[t];
    if (t < 32) sb2[t] = b2[t];
    if (t < 16) { sb3[t] = b3[t]; sb4[t] = b4[t]; }
    __syncthreads();

    {
        const int og = t & 15, rg = t >> 4;
        const int r0 = rg * 2, r1 = r0 + 1;
        ull a00 = ((const ull*)sb1)[og * 2];
        ull a01 = ((const ull*)sb1)[og * 2 + 1];
        ull a10 = a00, a11 = a01;
        const ull* w1u = (const ull*)sW1;
        #pragma unroll 4
        for (int k4 = 0; k4 < 32; k4++) {
            float4 x0 = *(const float4*)&sx[r0 * 132 + k4 * 4];
            float4 x1 = *(const float4*)&sx[r1 * 132 + k4 * 4];
            float xs0[4] = {x0.x, x0.y, x0.z, x0.w};
            float xs1[4] = {x1.x, x1.y, x1.z, x1.w};
            #pragma unroll
            for (int c = 0; c < 4; c++) {
                ulonglong2 w = *(const ulonglong2*)&w1u[(k4 * 4 + c) * 32 + og * 2];
                ull v0 = bcast2(xs0[c]);
                ull v1 = bcast2(xs1[c]);
                fma2(a00, v0, w.x); fma2(a01, v0, w.y);
                fma2(a10, v1, w.x); fma2(a11, v1, w.y);
            }
        }
        float p, q, r, s;
        unpack2(a00, p, q); unpack2(a01, r, s);
        *(float4*)&e1[r0 * 68 + og * 4] =
            make_float4(fmaxf(p, 0.f), fmaxf(q, 0.f), fmaxf(r, 0.f), fmaxf(s, 0.f));
        unpack2(a10, p, q); unpack2(a11, r, s);
        *(float4*)&e1[r1 * 68 + og * 4] =
            make_float4(fmaxf(p, 0.f), fmaxf(q, 0.f), fmaxf(r, 0.f), fmaxf(s, 0.f));
    }
    __syncthreads();

    const int row = t >> 3;
    const int e   = t & 7;

    {
        ull c0 = ((const ull*)sb2)[e * 2];
        ull c1 = ((const ull*)sb2)[e * 2 + 1];
        const float* h1r = &e1[row * 68];
        const ull* w2u = (const ull*)sW2;
        #pragma unroll 4
        for (int k4 = 0; k4 < 16; k4++) {
            float4 h = *(const float4*)&h1r[k4 * 4];
            float hs[4] = {h.x, h.y, h.z, h.w};
            #pragma unroll
            for (int c = 0; c < 4; c++) {
                ulonglong2 w = *(const ulonglong2*)&w2u[(k4 * 4 + c) * 16 + e * 2];
                ull hb = bcast2(hs[c]);
                fma2(c0, hb, w.x); fma2(c1, hb, w.y);
            }
        }
        float p, q, r, s;
        unpack2(c0, p, q); unpack2(c1, r, s);
        *(float4*)&e2[row * 36 + e * 4] =
            make_float4(fmaxf(p, 0.f), fmaxf(q, 0.f), fmaxf(r, 0.f), fmaxf(s, 0.f));
    }
    __syncthreads();

    {
        ull d0 = ((const ull*)sb3)[e];
        const float* h2r = &e2[row * 36];
        const ull* w3u = (const ull*)sW3;
        #pragma unroll
        for (int k4 = 0; k4 < 8; k4++) {
            float4 h = *(const float4*)&h2r[k4 * 4];
            float hs[4] = {h.x, h.y, h.z, h.w};
            #pragma unroll
            for (int c = 0; c < 4; c++)
                fma2(d0, bcast2(hs[c]), w3u[(k4 * 4 + c) * 8 + e]);
        }
        float p, q;
        unpack2(d0, p, q);
        *(float2*)&e3[row * 20 + e * 2] = make_float2(fmaxf(p, 0.f), fmaxf(q, 0.f));
    }
    __syncthreads();

    {
        ull f0 = ((const ull*)sb4)[e];
        const float* h3r = &e3[row * 20];
        const ull* w4u = (const ull*)sW4;
        #pragma unroll
        for (int k4 = 0; k4 < 4; k4++) {
            float4 h = *(const float4*)&h3r[k4 * 4];
            float hs[4] = {h.x, h.y, h.z, h.w};
            #pragma unroll
            for (int c = 0; c < 4; c++)
                fma2(f0, bcast2(hs[c]), w4u[(k4 * 4 + c) * 8 + e]);
        }
        float z0, z1;
        unpack2(f0, z0, z1);
        *(float2*)&g_z[(size_t)(i0 + row) * EMB + e * 2] = make_float2(z0, z1);

        float ps = z0 * z0 + z1 * z1;
        ps += __shfl_xor_sync(0xffffffffu, ps, 1);
        ps += __shfl_xor_sync(0xffffffffu, ps, 2);
        ps += __shfl_xor_sync(0xffffffffu, ps, 4);
        if (e == 0) g_sq[i0 + row] = ps;
    }
}

// ===========================================================================
// Rowsum staging/mma (128x128 tiles, 8i x 8j per thread) — measured-fast
// ===========================================================================
__device__ __forceinline__ void stage_a128(ull (*zasm)[130], int r0, int t) {
    const float4* gz4 = (const float4*)g_z;
    #pragma unroll
    for (int rr = 0; rr < 2; rr++) {
        int idx = t + rr * 256;
        int row = idx >> 2, kq = idx & 3;
        float4 f = gz4[(size_t)(r0 + row) * 4 + kq];
        *(float2*)&zasm[2 * kq][row]     = make_float2(f.x, f.y);
        *(float2*)&zasm[2 * kq + 1][row] = make_float2(f.z, f.w);
    }
}

__device__ __forceinline__ void stage_b128(ull (*zbsm)[68], int j0, int t) {
    const float4* gz4 = (const float4*)g_z;
    #pragma unroll
    for (int rr = 0; rr < 2; rr++) {
        int idx = t + rr * 256;
        int row = idx >> 2, kq = idx & 3;
        float4 f = gz4[(size_t)(j0 + row) * 4 + kq];
        int jp = row >> 1, lane = row & 1;
        int c = jp >> 1;
        int slot = 2 * ((c >> 1) + 16 * (c & 1)) + (jp & 1);
        ((float*)&zbsm[4 * kq + 0][slot])[lane] = f.x;
        ((float*)&zbsm[4 * kq + 1][slot])[lane] = f.y;
        ((float*)&zbsm[4 * kq + 2][slot])[lane] = f.z;
        ((float*)&zbsm[4 * kq + 3][slot])[lane] = f.w;
    }
}

__device__ __forceinline__ void mma88(ull* acc, const ull (*zasm)[130],
                                      const ull (*zbsm)[68], int tx, int ty) {
    #pragma unroll
    for (int k2 = 0; k2 < 8; k2++) {
        ulonglong2 aA = *(const ulonglong2*)&zasm[k2][8 * ty];
        ulonglong2 aB = *(const ulonglong2*)&zasm[k2][8 * ty + 2];
        ulonglong2 aC = *(const ulonglong2*)&zasm[k2][8 * ty + 4];
        ulonglong2 aD = *(const ulonglong2*)&zasm[k2][8 * ty + 6];
        ull apk[8] = {aA.x, aA.y, aB.x, aB.y, aC.x, aC.y, aD.x, aD.y};
        ulonglong2 be0 = *(const ulonglong2*)&zbsm[2 * k2][2 * tx];
        ulonglong2 be1 = *(const ulonglong2*)&zbsm[2 * k2][32 + 2 * tx];
        ulonglong2 bo0 = *(const ulonglong2*)&zbsm[2 * k2 + 1][2 * tx];
        ulonglong2 bo1 = *(const ulonglong2*)&zbsm[2 * k2 + 1][32 + 2 * tx];
        ull be[4] = {be0.x, be0.y, be1.x, be1.y};
        ull bo[4] = {bo0.x, bo0.y, bo1.x, bo1.y};
        #pragma unroll
        for (int r = 0; r < 8; r++) {
            float alo, ahi;
            unpack2(apk[r], alo, ahi);
            ull ae = bcast2(alo);
            ull ao = bcast2(ahi);
            #pragma unroll
            for (int m = 0; m < 4; m++) {
                fma2(acc[r * 4 + m], ae, be[m]);
                fma2(acc[r * 4 + m], ao, bo[m]);
            }
        }
    }
}

// ===========================================================================
// Kernel 2: symmetric row sums. 2080 blocks, 256 threads (measured ~38us)
// ===========================================================================
__global__ __launch_bounds__(256, 2) void rowsum_kernel()
{
    int by, bx;
    tri_decode(blockIdx.x, by, bx);

    __shared__ __align__(16) ull zasm[8][130];
    __shared__ __align__(16) ull zbsm[16][68];
    __shared__ __align__(16) ull sq1jp[64];
    __shared__ float sqis[128];
    __shared__ float rowacc[128];
    __shared__ float colacc[128];

    const int t = threadIdx.x, tx = t & 15, ty = t >> 4;
    const int i0 = by * 128, j0 = bx * 128;
    const bool diag = (bx == by);

    stage_a128(zasm, i0, t);
    stage_b128(zbsm, j0, t);
    if (t < 128) { sqis[t] = g_sq[i0 + t]; colacc[t] = 0.0f; }
    else if (t < 192) {
        int jp = t - 128;
        sq1jp[jp] = pack2f(1.0f + g_sq[j0 + 2 * jp], 1.0f + g_sq[j0 + 2 * jp + 1]);
    }
    __syncthreads();

    ull acc[32];
    #pragma unroll
    for (int m = 0; m < 32; m++) acc[m] = 0ull;
    mma88(acc, zasm, zbsm, tx, ty);

    ulonglong2 sjA = *(const ulonglong2*)&sq1jp[4 * tx];
    ulonglong2 sjB = *(const ulonglong2*)&sq1jp[4 * tx + 2];
    ull sj[4] = {sjA.x, sjA.y, sjB.x, sjB.y};
    const ull neg2 = bcast2(-2.0f);
    ull colp[4] = {0ull, 0ull, 0ull, 0ull};

    #pragma unroll
    for (int r = 0; r < 8; r++) {
        ull sid = bcast2(sqis[8 * ty + r]);
        float prow = 0.0f;
        #pragma unroll
        for (int m = 0; m < 4; m++) {
            ull d = add2(sid, sj[m]);
            fma2(d, acc[r * 4 + m], neg2);
            float e0, e1;
            unpack2(d, e0, e1);
            float n0 = frcp(e0), n1 = frcp(e1);
            prow += n0 + n1;
            colp[m] = add2(colp[m], pack2f(n0, n1));
        }
        float v = prow;
        v += __shfl_xor_sync(0xffffffffu, v, 1);
        v += __shfl_xor_sync(0xffffffffu, v, 2);
        v += __shfl_xor_sync(0xffffffffu, v, 4);
        v += __shfl_xor_sync(0xffffffffu, v, 8);
        if (tx == 0) rowacc[8 * ty + r] = v;
    }

    if (!diag) {
        #pragma unroll
        for (int m = 0; m < 4; m++) {
            ull c = colp[m];
            ull cs = __shfl_xor_sync(0xffffffffu, c, 16);
            c = add2(c, cs);
            if ((t & 16) == 0) {
                float lo, hi;
                unpack2(c, lo, hi);
                atomicAdd(&colacc[8 * tx + 2 * m], lo);
                atomicAdd(&colacc[8 * tx + 2 * m + 1], hi);
            }
        }
    }
    __syncthreads();

    if (t < 128) atomicAdd(&g_rowsum[i0 + t], rowacc[t]);
    if (!diag && t >= 128) atomicAdd(&g_rowsum[j0 + (t - 128)], colacc[t - 128]);
}

// ===========================================================================
// Writer staging/mma (64x64 tiles, 4i x 4j per thread) — R13 measured-best
// ===========================================================================
__device__ __forceinline__ void stage64(ull (*zsm)[66], int r0, int t) {
    const float4* gz4 = (const float4*)g_z;
    int row = t >> 2, q = t & 3;
    float4 f = gz4[(size_t)(r0 + row) * 4 + q];
    *(float2*)&zsm[2 * q][row]     = make_float2(f.x, f.y);
    *(float2*)&zsm[2 * q + 1][row] = make_float2(f.z, f.w);
}
__device__ __forceinline__ void stage64_swz(ull (*zsm)[66], int r0, int t) {
    const float4* gz4 = (const float4*)g_z;
    int row = t >> 2, q = t & 3;
    float4 f = gz4[(size_t)(r0 + row) * 4 + q];
    int p = bswz(row);
    *(float2*)&zsm[2 * q][p]     = make_float2(f.x, f.y);
    *(float2*)&zsm[2 * q + 1][p] = make_float2(f.z, f.w);
}

__device__ __forceinline__ void mma44_swz(ull* acc, const ull (*zasm)[66],
                                          const ull (*zbsm)[66], int tx, int ty) {
    #pragma unroll
    for (int k2 = 0; k2 < 8; k2++) {
        ulonglong2 b01 = *(const ulonglong2*)&zbsm[k2][2 * tx];
        ulonglong2 b23 = *(const ulonglong2*)&zbsm[k2][32 + 2 * tx];
        ulonglong2 a01 = *(const ulonglong2*)&zasm[k2][ty * 4];
        ulonglong2 a23 = *(const ulonglong2*)&zasm[k2][ty * 4 + 2];
        ull av[4] = {a01.x, a01.y, a23.x, a23.y};
        #pragma unroll
        for (int ii = 0; ii < 4; ii++) {
            fma2(acc[ii * 4 + 0], av[ii], b01.x);
            fma2(acc[ii * 4 + 1], av[ii], b01.y);
            fma2(acc[ii * 4 + 2], av[ii], b23.x);
            fma2(acc[ii * 4 + 3], av[ii], b23.y);
        }
    }
}

// ===========================================================================
// Kernel 3: symmetric writer. 8256 blocks, 256 threads. (R13 structure;
// epilogue clamp dropped: num = rcp(fma(-2, dot, (1+si)+sj)))
// ===========================================================================
__global__ __launch_bounds__(256) void writer_kernel(float* __restrict__ out)
{
    int by, bx;
    tri_decode128(blockIdx.x, by, bx);

    __shared__ ull zasm[8][66];
    __shared__ ull zbsm[8][66];
    __shared__ float snum[64 * 68];
    __shared__ float sq1is[64];
    __shared__ float sqjs[64];
    __shared__ float rinvi[64];
    __shared__ float rinvj[64];

    const int t = threadIdx.x, tx = t & 15, ty = t >> 4;
    const int i0 = by * 64, j0 = bx * 64;
    const bool diag = (bx == by);

    stage64(zasm, i0, t);
    stage64_swz(zbsm, j0, t);
    if (t < 64) sq1is[t] = 1.0f + g_sq[i0 + t];
    else if (t < 128) sqjs[t - 64] = g_sq[j0 + (t - 64)];
    else if (t < 192) rinvi[t - 128] = frcp(g_rowsum[i0 + (t - 128)]);
    else rinvj[t - 192] = frcp(g_rowsum[j0 + (t - 192)]);
    __syncthreads();

    ull acc[16];
    #pragma unroll
    for (int m = 0; m < 16; m++) acc[m] = 0ull;
    mma44_swz(acc, zasm, zbsm, tx, ty);

    const float4 sj4 = *(const float4*)&sqjs[4 * tx];

    #pragma unroll
    for (int ii = 0; ii < 4; ii++) {
        const int irow = ty * 4 + ii;
        const float c0 = sq1is[irow] + sj4.x;
        const float c1 = sq1is[irow] + sj4.y;
        const float c2 = sq1is[irow] + sj4.z;
        const float c3 = sq1is[irow] + sj4.w;
        const float rvi = rinvi[irow];
        float lo, hi;
        float4 n;

        unpack2(acc[ii * 4 + 0], lo, hi); n.x = frcp(fmaf(-2.0f, lo + hi, c0));
        unpack2(acc[ii * 4 + 1], lo, hi); n.y = frcp(fmaf(-2.0f, lo + hi, c1));
        unpack2(acc[ii * 4 + 2], lo, hi); n.z = frcp(fmaf(-2.0f, lo + hi, c2));
        unpack2(acc[ii * 4 + 3], lo, hi); n.w = frcp(fmaf(-2.0f, lo + hi, c3));

        if (!diag) *(float4*)&snum[irow * 68 + 4 * tx] = n;

        float4 v = make_float4(n.x * rvi, n.y * rvi, n.z * rvi, n.w * rvi);
        *(float4*)&out[(size_t)(i0 + irow) * N_PTS + j0 + 4 * tx] = v;
    }

    if (!diag) {
        __syncthreads();
        #pragma unroll
        for (int ii = 0; ii < 4; ii++) {
            const int jrow = ty * 4 + ii;
            const float rvj = rinvj[jrow];
            float* orow = &out[(size_t)(j0 + jrow) * N_PTS + i0];
            orow[tx]      = snum[(tx)      * 68 + jrow] * rvj;
            orow[tx + 16] = snum[(tx + 16) * 68 + jrow] * rvj;
            orow[tx + 32] = snum[(tx + 32) * 68 + jrow] * rvj;
            orow[tx + 48] = snum[(tx + 48) * 68 + jrow] * rvj;
        }
    }
}

// ---------------------------------------------------------------------------
extern "C" void kernel_launch(void* const* d_in, const int* in_sizes, int n_in,
                              void* d_out, int out_size)
{
    const float* x  = (const float*)d_in[0];
    const float* W1 = (const float*)d_in[1];
    const float* b1 = (const float*)d_in[2];
    const float* W2 = (const float*)d_in[3];
    const float* b2 = (const float*)d_in[4];
    const float* W3 = (const float*)d_in[5];
    const float* b3 = (const float*)d_in[6];
    const float* W4 = (const float*)d_in[7];
    const float* b4 = (const float*)d_in[8];
    float* out = (float*)d_out;

    cudaFuncSetAttribute(encoder_kernel,
                         cudaFuncAttributeMaxDynamicSharedMemorySize, ENC_SMEM);

    encoder_kernel<<<N_PTS / 32, 256, ENC_SMEM>>>(x, W1, b1, W2, b2, W3, b3, W4, b4);
    rowsum_kernel<<<(64 * 65) / 2, 256>>>();
    writer_kernel<<<(128 * 129) / 2, 256>>>(out);
}